// round 7
// baseline (speedup 1.0000x reference)
#include <cuda_runtime.h>
#include <cuda_bf16.h>
#include <math.h>
#include <stdint.h>

#define Bb 4
#define Nn 1024
#define Cc 1024
#define Hh 16
#define HD 64
#define NC 8
#define SCALEF 12.5f
#define NEG_BIG -1e30f

// ---------------- device scratch (allocation-free rule) ----------------
__device__ __nv_bfloat16 g_qh[Bb*Hh*Nn*HD], g_ql[Bb*Hh*Nn*HD];
__device__ __nv_bfloat16 g_kh[Bb*Hh*Nn*HD], g_kl[Bb*Hh*Nn*HD];
__device__ __nv_bfloat16 g_vh[Bb*Hh*Nn*HD], g_vl[Bb*Hh*Nn*HD];
__device__ __nv_bfloat16 g_xh[4096 * 1024], g_xl[4096 * 1024];
__device__ __nv_bfloat16 g_w1h[3072 * 1024], g_w1l[3072 * 1024];
__device__ __nv_bfloat16 g_ah[4096 * 1024], g_al[4096 * 1024];
__device__ __nv_bfloat16 g_w2h[1024 * 1024], g_w2l[1024 * 1024];

__device__ __forceinline__ void split2(float a, float b, uint32_t& h, uint32_t& l)
{
    __nv_bfloat162 hh = __floats2bfloat162_rn(a, b);
    float la = a - __bfloat162float(hh.x);
    float lb = b - __bfloat162float(hh.y);
    __nv_bfloat162 ll = __floats2bfloat162_rn(la, lb);
    h = *(uint32_t*)&hh; l = *(uint32_t*)&ll;
}

// ---------------------------------------------------------------------------
// split fp32 -> (hi, lo) bf16.  DST: 0=x, 1=qkv_w, 3=proj_w
// ---------------------------------------------------------------------------
template <int DST>
__global__ __launch_bounds__(256) void split_kernel(const float* __restrict__ src)
{
    const int i = (blockIdx.x * 256 + threadIdx.x) * 4;
    float4 v = *(const float4*)(src + i);
    __nv_bfloat16 h[4], l[4];
    const float f[4] = {v.x, v.y, v.z, v.w};
#pragma unroll
    for (int j = 0; j < 4; j++) {
        h[j] = __float2bfloat16(f[j]);
        l[j] = __float2bfloat16(f[j] - __bfloat162float(h[j]));
    }
    __nv_bfloat16* hp;
    __nv_bfloat16* lp;
    if (DST == 0) { hp = g_xh;  lp = g_xl;  }
    else if (DST == 1) { hp = g_w1h; lp = g_w1l; }
    else { hp = g_w2h; lp = g_w2l; }
    *(uint2*)(hp + i) = *(const uint2*)h;
    *(uint2*)(lp + i) = *(const uint2*)l;
}

// ---------------------------------------------------------------------------
// common PTX helpers
// ---------------------------------------------------------------------------
__device__ __forceinline__ void cpasync16(void* dst, const void* src)
{
    uint32_t d = (uint32_t)__cvta_generic_to_shared(dst);
    asm volatile("cp.async.cg.shared.global [%0], [%1], 16;\n" :: "r"(d), "l"(src));
}
#define CP_COMMIT() asm volatile("cp.async.commit_group;\n" ::)
#define CP_WAIT0()  asm volatile("cp.async.wait_group 0;\n" ::)
#define CP_WAIT1()  asm volatile("cp.async.wait_group 1;\n" ::)

#define LDSM4(R, addr)                                                        \
    asm volatile("ldmatrix.sync.aligned.m8n8.x4.shared.b16 {%0,%1,%2,%3}, [%4];" \
                 : "=r"(R[0]), "=r"(R[1]), "=r"(R[2]), "=r"(R[3]) : "r"(addr));
#define LDSM4T(R, addr)                                                       \
    asm volatile("ldmatrix.sync.aligned.m8n8.x4.trans.shared.b16 {%0,%1,%2,%3}, [%4];" \
                 : "=r"(R[0]), "=r"(R[1]), "=r"(R[2]), "=r"(R[3]) : "r"(addr));

#define MMA16816(d, a, b0, b1)                                                \
    asm volatile("mma.sync.aligned.m16n8k16.row.col.f32.bf16.bf16.f32 "       \
                 "{%0,%1,%2,%3},{%4,%5,%6,%7},{%8,%9},{%0,%1,%2,%3};"         \
                 : "+f"(d[0]), "+f"(d[1]), "+f"(d[2]), "+f"(d[3])             \
                 : "r"(a[0]), "r"(a[1]), "r"(a[2]), "r"(a[3]), "r"(b0), "r"(b1));

// ---------------------------------------------------------------------------
// Tensor-core GEMM (split bf16, 3-MMA):  C[M x Nout] = A @ W^T + bias
// MODE 0: A = x, W = qkv_w -> scatter split bf16 into g_{q,k,v}{h,l}
// MODE 1: A = att (g_ah/g_al), W = proj_w -> fp32 out
// 128x128 tile, BK=32, 2-stage cp.async. __launch_bounds__(256, 2) so two
// CTAs co-reside per SM: one fills the tensor pipe while the other is at a
// barrier / in ldmatrix latency.
// ---------------------------------------------------------------------------
#define SKP 40
#define STG (128 * SKP)
#define ARR (2 * STG)
#define SMEM_BYTES (4 * ARR * 2)

template <int MODE>
__global__ __launch_bounds__(256, 2) void mma_gemm_kernel(
    const float* __restrict__ bias, float* __restrict__ out, int Nout)
{
    extern __shared__ __nv_bfloat16 sm[];
    __nv_bfloat16* sAh = sm;
    __nv_bfloat16* sAl = sm + ARR;
    __nv_bfloat16* sBh = sm + 2 * ARR;
    __nv_bfloat16* sBl = sm + 3 * ARR;

    const int K = 1024;
    const int tid = threadIdx.x;
    const int lane = tid & 31;
    const int warp = tid >> 5;
    const int wm = warp & 3;
    const int wn = warp >> 2;
    const int bm0 = blockIdx.y * 128;
    const int bn0 = blockIdx.x * 128;

    const __nv_bfloat16* Ah = (MODE == 0) ? g_xh : g_ah;
    const __nv_bfloat16* Al = (MODE == 0) ? g_xl : g_al;
    const __nv_bfloat16* Wh = (MODE == 0) ? g_w1h : g_w2h;
    const __nv_bfloat16* Wl = (MODE == 0) ? g_w1l : g_w2l;

    const int id0 = tid, id1 = tid + 256;
    const int r0 = id0 >> 2, s0 = id0 & 3;
    const int r1 = id1 >> 2, s1 = id1 & 3;

    const uint32_t a_lane = (uint32_t)((lane & 15) * (SKP * 2) + (lane >> 4) * 16);
    const uint32_t b_lane = (uint32_t)(((lane & 7) + ((lane >> 4) << 3)) * (SKP * 2)
                                       + ((lane >> 3) & 1) * 16);

    const uint32_t sAh_u = (uint32_t)__cvta_generic_to_shared(sAh);
    const uint32_t sAl_u = (uint32_t)__cvta_generic_to_shared(sAl);
    const uint32_t sBh_u = (uint32_t)__cvta_generic_to_shared(sBh);
    const uint32_t sBl_u = (uint32_t)__cvta_generic_to_shared(sBl);

    // precomputed global source offsets (bytes kept in pointers)
    const __nv_bfloat16* gA0 = Ah + (size_t)(bm0 + r0) * K + s0 * 8;
    const __nv_bfloat16* gA1 = Ah + (size_t)(bm0 + r1) * K + s1 * 8;
    const __nv_bfloat16* gAl0 = Al + (size_t)(bm0 + r0) * K + s0 * 8;
    const __nv_bfloat16* gAl1 = Al + (size_t)(bm0 + r1) * K + s1 * 8;
    const __nv_bfloat16* gB0 = Wh + (size_t)(bn0 + r0) * K + s0 * 8;
    const __nv_bfloat16* gB1 = Wh + (size_t)(bn0 + r1) * K + s1 * 8;
    const __nv_bfloat16* gBl0 = Wl + (size_t)(bn0 + r0) * K + s0 * 8;
    const __nv_bfloat16* gBl1 = Wl + (size_t)(bn0 + r1) * K + s1 * 8;
    const int d0 = r0 * SKP + s0 * 8;
    const int d1 = r1 * SKP + s1 * 8;

    float acc[2][8][4];
#pragma unroll
    for (int i = 0; i < 2; i++)
#pragma unroll
        for (int j = 0; j < 8; j++)
#pragma unroll
            for (int c = 0; c < 4; c++) acc[i][j][c] = 0.0f;

    auto prefetch = [&](int it) {
        const int st = it & 1;
        const int k0 = it * 32;
        __nv_bfloat16* base = sm + st * STG;
        cpasync16(base + d0, gA0 + k0);
        cpasync16(base + d1, gA1 + k0);
        cpasync16(base + ARR + d0, gAl0 + k0);
        cpasync16(base + ARR + d1, gAl1 + k0);
        cpasync16(base + 2 * ARR + d0, gB0 + k0);
        cpasync16(base + 2 * ARR + d1, gB1 + k0);
        cpasync16(base + 3 * ARR + d0, gBl0 + k0);
        cpasync16(base + 3 * ARR + d1, gBl1 + k0);
        CP_COMMIT();
    };

    const int NIT = K / 32;
    prefetch(0);

    for (int it = 0; it < NIT; it++) {
        if (it + 1 < NIT) { prefetch(it + 1); CP_WAIT1(); }
        else              { CP_WAIT0(); }
        __syncthreads();

        const int st = it & 1;
        const uint32_t stOff = (uint32_t)(st * STG * 2);
        const uint32_t aBase = stOff + (uint32_t)(wm * 32) * (SKP * 2) + a_lane;
        const uint32_t bBase = stOff + (uint32_t)(wn * 64) * (SKP * 2) + b_lane;

#pragma unroll
        for (int ks = 0; ks < 2; ks++) {
            const uint32_t kb = (uint32_t)(ks * 32);
            uint32_t ah[2][4], al[2][4];
#pragma unroll
            for (int mt = 0; mt < 2; mt++) {
                const uint32_t off = aBase + (uint32_t)(mt * 16) * (SKP * 2) + kb;
                LDSM4(ah[mt], sAh_u + off);
                LDSM4(al[mt], sAl_u + off);
            }
            // B fragments loaded per p-group to keep register liveness low
#pragma unroll
            for (int p = 0; p < 4; p++) {
                uint32_t bh[4], bl[4];
                const uint32_t off = bBase + (uint32_t)(p * 16) * (SKP * 2) + kb;
                LDSM4(bh, sBh_u + off);
                LDSM4(bl, sBl_u + off);
#pragma unroll
                for (int mt = 0; mt < 2; mt++) {
#pragma unroll
                    for (int qq = 0; qq < 2; qq++) {
                        const int nt = p * 2 + qq;
                        const int q2 = qq * 2;
                        MMA16816(acc[mt][nt], ah[mt], bh[q2], bh[q2 + 1]);
                        MMA16816(acc[mt][nt], ah[mt], bl[q2], bl[q2 + 1]);
                        MMA16816(acc[mt][nt], al[mt], bh[q2], bh[q2 + 1]);
                    }
                }
            }
        }
        __syncthreads();
    }

    const int gid = lane >> 2, tig = lane & 3;
#pragma unroll
    for (int mt = 0; mt < 2; mt++) {
#pragma unroll
        for (int nt = 0; nt < 8; nt++) {
            const int m = bm0 + wm * 32 + mt * 16 + gid;
            const int n = bn0 + wn * 64 + nt * 8 + tig * 2;
            const float b0 = bias[n], b1 = bias[n + 1];
            const float v00 = acc[mt][nt][0] + b0, v01 = acc[mt][nt][1] + b1;
            const float v10 = acc[mt][nt][2] + b0, v11 = acc[mt][nt][3] + b1;
            if (MODE == 0) {
                const int which = n >> 10;
                const int cc = n & 1023;
                const int h = cc >> 6, d = cc & 63;
                __nv_bfloat16 *dh, *dl;
                if (which == 0)      { dh = g_qh; dl = g_ql; }
                else if (which == 1) { dh = g_kh; dl = g_kl; }
                else                 { dh = g_vh; dl = g_vl; }
                const int bbi0 = m >> 10, nr0 = m & 1023;
                const int bbi1 = (m + 8) >> 10, nr1 = (m + 8) & 1023;
                uint32_t hh, ll;
                split2(v00, v01, hh, ll);
                size_t off0 = (size_t)(((bbi0 * Hh) + h) * Nn + nr0) * HD + d;
                *(uint32_t*)(dh + off0) = hh; *(uint32_t*)(dl + off0) = ll;
                split2(v10, v11, hh, ll);
                size_t off1 = (size_t)(((bbi1 * Hh) + h) * Nn + nr1) * HD + d;
                *(uint32_t*)(dh + off1) = hh; *(uint32_t*)(dl + off1) = ll;
            } else {
                *(float2*)(out + (size_t)m * Nout + n) = make_float2(v00, v01);
                *(float2*)(out + (size_t)(m + 8) * Nout + n) = make_float2(v10, v11);
            }
        }
    }
}

// ---------------------------------------------------------------------------
// Tensor-core fused attention (split bf16, 3-MMA) — unchanged from R4
// ---------------------------------------------------------------------------
#define SKP2 72
#define RS2 (SKP2 * 2)
#define OFF_QH 0
#define OFF_QL 9216
#define OFF_KH 18432
#define OFF_KL 27648
#define OFF_VH 36864
#define OFF_VL 46080
#define KV_STG 4608
#define ATTN_SMEM (55296 * 2)

__global__ __launch_bounds__(256, 1) void attn_mma_kernel(
    const float* __restrict__ diag_strength,
    const float* __restrict__ band_bias,
    const float* __restrict__ noise,
    const unsigned char* __restrict__ mask)
{
    extern __shared__ __nv_bfloat16 sm2[];

    const int tid = threadIdx.x;
    const int lane = tid & 31;
    const int warp = tid >> 5;
    const int nb = blockIdx.x;
    const int h = blockIdx.y;
    const int b = blockIdx.z;
    const bool causal = (h < NC);
    const float ds = causal ? diag_strength[b * NC + h] : 0.0f;
    const int bh = b * Hh + h;

    const int g = lane >> 2, t = lane & 3;
    const int q0 = nb * 128 + warp * 16;
    const int rg0 = q0 + g, rg1 = q0 + g + 8;
    const int diagtile = q0 >> 6;
    const int ntiles = causal ? (2 * nb + 2) : 16;

    const size_t qg = ((size_t)bh * Nn + nb * 128) * HD;
#pragma unroll
    for (int j = 0; j < 4; j++) {
        const int c = tid + j * 256;
        const int row = c >> 3, c8 = c & 7;
        const int dd = row * SKP2 + c8 * 8;
        const size_t sg = qg + row * HD + c8 * 8;
        cpasync16(sm2 + OFF_QH + dd, g_qh + sg);
        cpasync16(sm2 + OFF_QL + dd, g_ql + sg);
    }
    auto prefetchKV = [&](int mb) {
        const int st = mb & 1;
        const size_t kv = ((size_t)bh * Nn + mb * 64) * HD;
#pragma unroll
        for (int j = 0; j < 2; j++) {
            const int c = tid + j * 256;
            const int row = c >> 3, c8 = c & 7;
            const int dd = st * KV_STG + row * SKP2 + c8 * 8;
            const size_t sg = kv + row * HD + c8 * 8;
            cpasync16(sm2 + OFF_KH + dd, g_kh + sg);
            cpasync16(sm2 + OFF_KL + dd, g_kl + sg);
            cpasync16(sm2 + OFF_VH + dd, g_vh + sg);
            cpasync16(sm2 + OFF_VL + dd, g_vl + sg);
        }
        CP_COMMIT();
    };
    prefetchKV(0);
    CP_WAIT0();
    __syncthreads();

    const uint32_t sQh_u = (uint32_t)__cvta_generic_to_shared(sm2 + OFF_QH);
    const uint32_t sQl_u = (uint32_t)__cvta_generic_to_shared(sm2 + OFF_QL);
    const uint32_t sKh_u = (uint32_t)__cvta_generic_to_shared(sm2 + OFF_KH);
    const uint32_t sKl_u = (uint32_t)__cvta_generic_to_shared(sm2 + OFF_KL);
    const uint32_t sVh_u = (uint32_t)__cvta_generic_to_shared(sm2 + OFF_VH);
    const uint32_t sVl_u = (uint32_t)__cvta_generic_to_shared(sm2 + OFF_VL);

    const uint32_t a_lane = (uint32_t)((lane & 15) * RS2 + (lane >> 4) * 16);
    const uint32_t b_lane = (uint32_t)(((lane & 7) + ((lane >> 4) << 3)) * RS2
                                       + ((lane >> 3) & 1) * 16);

    uint32_t qfh[4][4], qfl[4][4];
    {
        const uint32_t qa = (uint32_t)(warp * 16) * RS2 + a_lane;
#pragma unroll
        for (int ks = 0; ks < 4; ks++) {
            LDSM4(qfh[ks], sQh_u + qa + ks * 32);
            LDSM4(qfl[ks], sQl_u + qa + ks * 32);
        }
    }

    float o[8][4];
#pragma unroll
    for (int i = 0; i < 8; i++)
#pragma unroll
        for (int j = 0; j < 4; j++) o[i][j] = 0.0f;
    float rmax0 = NEG_BIG, rmax1 = NEG_BIG, rsum0 = 0.0f, rsum1 = 0.0f;

    const size_t nm_base = (size_t)bh << 20;
    const float* bbp = causal ? band_bias : (band_bias + ((size_t)(h - NC) << 20));

    for (int mb = 0; mb < ntiles; mb++) {
        if (mb + 1 < ntiles) prefetchKV(mb + 1);

        const bool active = !(causal && mb > diagtile);
        if (active) {
            const uint32_t kst = (uint32_t)((mb & 1) * KV_STG * 2);

            float s[8][4];
#pragma unroll
            for (int i = 0; i < 8; i++)
#pragma unroll
                for (int j = 0; j < 4; j++) s[i][j] = 0.0f;
#pragma unroll
            for (int ks = 0; ks < 4; ks++) {
                uint32_t kfh[4][4], kfl[4][4];
#pragma unroll
                for (int p = 0; p < 4; p++) {
                    const uint32_t off = kst + (uint32_t)(p * 16) * RS2 + b_lane + ks * 32;
                    LDSM4(kfh[p], sKh_u + off);
                    LDSM4(kfl[p], sKl_u + off);
                }
#pragma unroll
                for (int p = 0; p < 4; p++) {
#pragma unroll
                    for (int qq = 0; qq < 2; qq++) {
                        const int nt = p * 2 + qq;
                        const int q2 = qq * 2;
                        MMA16816(s[nt], qfh[ks], kfh[p][q2], kfh[p][q2 + 1]);
                        MMA16816(s[nt], qfh[ks], kfl[p][q2], kfl[p][q2 + 1]);
                        MMA16816(s[nt], qfl[ks], kfh[p][q2], kfh[p][q2 + 1]);
                    }
                }
            }

            const int cb0 = mb * 64 + t * 2;
#pragma unroll
            for (int nt = 0; nt < 8; nt++) {
                const int c = cb0 + nt * 8;
                const size_t o0 = nm_base + ((size_t)rg0 << 10) + c;
                const size_t o1 = nm_base + ((size_t)rg1 << 10) + c;
                const float2 nz0 = *(const float2*)(noise + o0);
                const float2 nz1 = *(const float2*)(noise + o1);
                const uchar2 m0 = *(const uchar2*)(mask + o0);
                const uchar2 m1 = *(const uchar2*)(mask + o1);
                s[nt][0] = s[nt][0] * SCALEF + (m0.x ? nz0.x : 0.0f);
                s[nt][1] = s[nt][1] * SCALEF + (m0.y ? nz0.y : 0.0f);
                s[nt][2] = s[nt][2] * SCALEF + (m1.x ? nz1.x : 0.0f);
                s[nt][3] = s[nt][3] * SCALEF + (m1.y ? nz1.y : 0.0f);
                if (!causal) {
                    const float2 b0v = *(const float2*)(bbp + ((size_t)rg0 << 10) + c);
                    const float2 b1v = *(const float2*)(bbp + ((size_t)rg1 << 10) + c);
                    s[nt][0] += b0v.x; s[nt][1] += b0v.y;
                    s[nt][2] += b1v.x; s[nt][3] += b1v.y;
                } else if (mb == diagtile) {
                    if (c > rg0)           s[nt][0] = NEG_BIG;
                    else if (c == rg0)     s[nt][0] += ds;
                    if (c + 1 > rg0)       s[nt][1] = NEG_BIG;
                    else if (c + 1 == rg0) s[nt][1] += ds;
                    if (c > rg1)           s[nt][2] = NEG_BIG;
                    else if (c == rg1)     s[nt][2] += ds;
                    if (c + 1 > rg1)       s[nt][3] = NEG_BIG;
                    else if (c + 1 == rg1) s[nt][3] += ds;
                }
            }

            float mx0 = NEG_BIG, mx1 = NEG_BIG;
#pragma unroll
            for (int nt = 0; nt < 8; nt++) {
                mx0 = fmaxf(mx0, fmaxf(s[nt][0], s[nt][1]));
                mx1 = fmaxf(mx1, fmaxf(s[nt][2], s[nt][3]));
            }
            mx0 = fmaxf(mx0, __shfl_xor_sync(0xffffffffu, mx0, 1));
            mx0 = fmaxf(mx0, __shfl_xor_sync(0xffffffffu, mx0, 2));
            mx1 = fmaxf(mx1, __shfl_xor_sync(0xffffffffu, mx1, 1));
            mx1 = fmaxf(mx1, __shfl_xor_sync(0xffffffffu, mx1, 2));
            const float nm0 = fmaxf(rmax0, mx0);
            const float nm1 = fmaxf(rmax1, mx1);
            const float al0 = __expf(rmax0 - nm0);
            const float al1 = __expf(rmax1 - nm1);
            rmax0 = nm0; rmax1 = nm1;
            float ts0 = 0.0f, ts1 = 0.0f;
#pragma unroll
            for (int nt = 0; nt < 8; nt++) {
                s[nt][0] = __expf(s[nt][0] - nm0);
                s[nt][1] = __expf(s[nt][1] - nm0);
                s[nt][2] = __expf(s[nt][2] - nm1);
                s[nt][3] = __expf(s[nt][3] - nm1);
                ts0 += s[nt][0] + s[nt][1];
                ts1 += s[nt][2] + s[nt][3];
            }
            ts0 += __shfl_xor_sync(0xffffffffu, ts0, 1);
            ts0 += __shfl_xor_sync(0xffffffffu, ts0, 2);
            ts1 += __shfl_xor_sync(0xffffffffu, ts1, 1);
            ts1 += __shfl_xor_sync(0xffffffffu, ts1, 2);
            rsum0 = rsum0 * al0 + ts0;
            rsum1 = rsum1 * al1 + ts1;
#pragma unroll
            for (int nt = 0; nt < 8; nt++) {
                o[nt][0] *= al0; o[nt][1] *= al0;
                o[nt][2] *= al1; o[nt][3] *= al1;
            }

#pragma unroll
            for (int ks = 0; ks < 4; ks++) {
                uint32_t pah[4], pal[4];
                split2(s[2 * ks][0],     s[2 * ks][1],     pah[0], pal[0]);
                split2(s[2 * ks][2],     s[2 * ks][3],     pah[1], pal[1]);
                split2(s[2 * ks + 1][0], s[2 * ks + 1][1], pah[2], pal[2]);
                split2(s[2 * ks + 1][2], s[2 * ks + 1][3], pah[3], pal[3]);
#pragma unroll
                for (int dp = 0; dp < 4; dp++) {
                    uint32_t vfh[4], vfl[4];
                    const uint32_t off = kst + (uint32_t)(ks * 16) * RS2 + dp * 32 + a_lane;
                    LDSM4T(vfh, sVh_u + off);
                    LDSM4T(vfl, sVl_u + off);
                    const int nt0 = dp * 2, nt1 = dp * 2 + 1;
                    MMA16816(o[nt0], pah, vfh[0], vfh[1]);
                    MMA16816(o[nt0], pah, vfl[0], vfl[1]);
                    MMA16816(o[nt0], pal, vfh[0], vfh[1]);
                    MMA16816(o[nt1], pah, vfh[2], vfh[3]);
                    MMA16816(o[nt1], pah, vfl[2], vfl[3]);
                    MMA16816(o[nt1], pal, vfh[2], vfh[3]);
                }
            }
        }

        if (mb + 1 < ntiles) CP_WAIT0();
        __syncthreads();
    }

    const float inv0 = 1.0f / rsum0;
    const float inv1 = 1.0f / rsum1;
#pragma unroll
    for (int nt = 0; nt < 8; nt++) {
        const int d = h * HD + nt * 8 + t * 2;
        uint32_t hh, ll;
        const size_t off0 = ((size_t)b * Nn + rg0) * Cc + d;
        split2(o[nt][0] * inv0, o[nt][1] * inv0, hh, ll);
        *(uint32_t*)(g_ah + off0) = hh; *(uint32_t*)(g_al + off0) = ll;
        const size_t off1 = ((size_t)b * Nn + rg1) * Cc + d;
        split2(o[nt][2] * inv1, o[nt][3] * inv1, hh, ll);
        *(uint32_t*)(g_ah + off1) = hh; *(uint32_t*)(g_al + off1) = ll;
    }
}

// ---------------------------------------------------------------------------
extern "C" void kernel_launch(void* const* d_in, const int* in_sizes, int n_in,
                              void* d_out, int out_size)
{
    const float* x       = (const float*)d_in[0];
    const float* qkv_w   = (const float*)d_in[1];
    const float* qkv_b   = (const float*)d_in[2];
    const float* proj_w  = (const float*)d_in[3];
    const float* proj_b  = (const float*)d_in[4];
    const float* dstr    = (const float*)d_in[5];
    const float* bband   = (const float*)d_in[6];
    const float* noise   = (const float*)d_in[7];
    const unsigned char* smask = (const unsigned char*)d_in[8];
    float* out = (float*)d_out;

    cudaFuncSetAttribute(mma_gemm_kernel<0>,
                         cudaFuncAttributeMaxDynamicSharedMemorySize, SMEM_BYTES);
    cudaFuncSetAttribute(mma_gemm_kernel<1>,
                         cudaFuncAttributeMaxDynamicSharedMemorySize, SMEM_BYTES);
    cudaFuncSetAttribute(attn_mma_kernel,
                         cudaFuncAttributeMaxDynamicSharedMemorySize, ATTN_SMEM);

    // 1) split fp32 inputs to (hi, lo) bf16
    split_kernel<0><<<4096 * 1024 / 1024, 256>>>(x);
    split_kernel<1><<<3072 * 1024 / 1024, 256>>>(qkv_w);
    split_kernel<3><<<1024 * 1024 / 1024, 256>>>(proj_w);

    // 2) QKV projection -> split bf16 q/k/v
    dim3 g1(3072 / 128, 4096 / 128);
    mma_gemm_kernel<0><<<g1, 256, SMEM_BYTES>>>(qkv_b, nullptr, 3072);

    // 3) fused tensor-core attention -> split bf16 att
    dim3 g2(Nn / 128, Hh, Bb);
    attn_mma_kernel<<<g2, 256, ATTN_SMEM>>>(dstr, bband, noise, smask);

    // 4) output projection
    dim3 g3(1024 / 128, 4096 / 128);
    mma_gemm_kernel<1><<<g3, 256, SMEM_BYTES>>>(proj_b, out, 1024);
}

// round 8
// speedup vs baseline: 1.0264x; 1.0264x over previous
#include <cuda_runtime.h>
#include <cuda_bf16.h>
#include <math.h>
#include <stdint.h>

#define Bb 4
#define Nn 1024
#define Cc 1024
#define Hh 16
#define HD 64
#define NC 8
#define SCALEF 12.5f
#define NEG_BIG -1e30f

// ---------------- device scratch (allocation-free rule) ----------------
__device__ __nv_bfloat16 g_qh[Bb*Hh*Nn*HD], g_ql[Bb*Hh*Nn*HD];
__device__ __nv_bfloat16 g_kh[Bb*Hh*Nn*HD], g_kl[Bb*Hh*Nn*HD];
__device__ __nv_bfloat16 g_vh[Bb*Hh*Nn*HD], g_vl[Bb*Hh*Nn*HD];
__device__ __nv_bfloat16 g_xh[4096 * 1024], g_xl[4096 * 1024];
__device__ __nv_bfloat16 g_w1h[3072 * 1024], g_w1l[3072 * 1024];
__device__ __nv_bfloat16 g_ah[4096 * 1024], g_al[4096 * 1024];
__device__ __nv_bfloat16 g_w2h[1024 * 1024], g_w2l[1024 * 1024];

__device__ __forceinline__ void split2(float a, float b, uint32_t& h, uint32_t& l)
{
    __nv_bfloat162 hh = __floats2bfloat162_rn(a, b);
    float la = a - __bfloat162float(hh.x);
    float lb = b - __bfloat162float(hh.y);
    __nv_bfloat162 ll = __floats2bfloat162_rn(la, lb);
    h = *(uint32_t*)&hh; l = *(uint32_t*)&ll;
}

// ---------------------------------------------------------------------------
// fused split: one grid covers x (4M), qkv_w (3M), proj_w (1M) fp32 elems
// ---------------------------------------------------------------------------
#define XN (4096 * 1024)
#define W1N (3072 * 1024)
#define W2N (1024 * 1024)

__global__ __launch_bounds__(256) void split_all_kernel(
    const float* __restrict__ x, const float* __restrict__ w1,
    const float* __restrict__ w2)
{
    const int i = (blockIdx.x * 256 + threadIdx.x) * 4;
    const float* src;
    __nv_bfloat16 *hp, *lp;
    int off;
    if (i < XN)            { src = x;  hp = g_xh;  lp = g_xl;  off = i; }
    else if (i < XN + W1N) { src = w1; hp = g_w1h; lp = g_w1l; off = i - XN; }
    else                   { src = w2; hp = g_w2h; lp = g_w2l; off = i - XN - W1N; }

    float4 v = *(const float4*)(src + off);
    __nv_bfloat16 h[4], l[4];
    const float f[4] = {v.x, v.y, v.z, v.w};
#pragma unroll
    for (int j = 0; j < 4; j++) {
        h[j] = __float2bfloat16(f[j]);
        l[j] = __float2bfloat16(f[j] - __bfloat162float(h[j]));
    }
    *(uint2*)(hp + off) = *(const uint2*)h;
    *(uint2*)(lp + off) = *(const uint2*)l;
}

// ---------------------------------------------------------------------------
// common PTX helpers
// ---------------------------------------------------------------------------
__device__ __forceinline__ void cpasync16(void* dst, const void* src)
{
    uint32_t d = (uint32_t)__cvta_generic_to_shared(dst);
    asm volatile("cp.async.cg.shared.global [%0], [%1], 16;\n" :: "r"(d), "l"(src));
}
#define CP_COMMIT() asm volatile("cp.async.commit_group;\n" ::)
#define CP_WAIT0()  asm volatile("cp.async.wait_group 0;\n" ::)

#define LDSM4(R, addr)                                                        \
    asm volatile("ldmatrix.sync.aligned.m8n8.x4.shared.b16 {%0,%1,%2,%3}, [%4];" \
                 : "=r"(R[0]), "=r"(R[1]), "=r"(R[2]), "=r"(R[3]) : "r"(addr));
#define LDSM4T(R, addr)                                                       \
    asm volatile("ldmatrix.sync.aligned.m8n8.x4.trans.shared.b16 {%0,%1,%2,%3}, [%4];" \
                 : "=r"(R[0]), "=r"(R[1]), "=r"(R[2]), "=r"(R[3]) : "r"(addr));

#define MMA16816(d, a, b0, b1)                                                \
    asm volatile("mma.sync.aligned.m16n8k16.row.col.f32.bf16.bf16.f32 "       \
                 "{%0,%1,%2,%3},{%4,%5,%6,%7},{%8,%9},{%0,%1,%2,%3};"         \
                 : "+f"(d[0]), "+f"(d[1]), "+f"(d[2]), "+f"(d[3])             \
                 : "r"(a[0]), "r"(a[1]), "r"(a[2]), "r"(a[3]), "r"(b0), "r"(b1));

// ---------------------------------------------------------------------------
// Tensor-core GEMM (split bf16, 3-MMA):  C[M x Nout] = A @ W^T + bias
// Single-barrier pipeline: { wait; sync; prefetch(it+1); compute(it) }.
// The one barrier proves stage-it arrived AND stage (it+1)&1 drained.
// __launch_bounds__(256, 2): two CTAs per SM keep the tensor pipe fed.
// ---------------------------------------------------------------------------
#define SKP 40
#define STG (128 * SKP)
#define ARR (2 * STG)
#define SMEM_BYTES (4 * ARR * 2)

template <int MODE>
__global__ __launch_bounds__(256, 2) void mma_gemm_kernel(
    const float* __restrict__ bias, float* __restrict__ out, int Nout)
{
    extern __shared__ __nv_bfloat16 sm[];

    const int K = 1024;
    const int tid = threadIdx.x;
    const int lane = tid & 31;
    const int warp = tid >> 5;
    const int wm = warp & 3;
    const int wn = warp >> 2;
    const int bm0 = blockIdx.y * 128;
    const int bn0 = blockIdx.x * 128;

    const __nv_bfloat16* Ah = (MODE == 0) ? g_xh : g_ah;
    const __nv_bfloat16* Al = (MODE == 0) ? g_xl : g_al;
    const __nv_bfloat16* Wh = (MODE == 0) ? g_w1h : g_w2h;
    const __nv_bfloat16* Wl = (MODE == 0) ? g_w1l : g_w2l;

    const int id0 = tid, id1 = tid + 256;
    const int r0 = id0 >> 2, s0 = id0 & 3;
    const int r1 = id1 >> 2, s1 = id1 & 3;

    const uint32_t a_lane = (uint32_t)((lane & 15) * (SKP * 2) + (lane >> 4) * 16);
    const uint32_t b_lane = (uint32_t)(((lane & 7) + ((lane >> 4) << 3)) * (SKP * 2)
                                       + ((lane >> 3) & 1) * 16);

    const uint32_t sAh_u = (uint32_t)__cvta_generic_to_shared(sm);
    const uint32_t sAl_u = sAh_u + ARR * 2;
    const uint32_t sBh_u = sAh_u + 2 * ARR * 2;
    const uint32_t sBl_u = sAh_u + 3 * ARR * 2;

    const __nv_bfloat16* gA0 = Ah + (size_t)(bm0 + r0) * K + s0 * 8;
    const __nv_bfloat16* gA1 = Ah + (size_t)(bm0 + r1) * K + s1 * 8;
    const __nv_bfloat16* gAl0 = Al + (size_t)(bm0 + r0) * K + s0 * 8;
    const __nv_bfloat16* gAl1 = Al + (size_t)(bm0 + r1) * K + s1 * 8;
    const __nv_bfloat16* gB0 = Wh + (size_t)(bn0 + r0) * K + s0 * 8;
    const __nv_bfloat16* gB1 = Wh + (size_t)(bn0 + r1) * K + s1 * 8;
    const __nv_bfloat16* gBl0 = Wl + (size_t)(bn0 + r0) * K + s0 * 8;
    const __nv_bfloat16* gBl1 = Wl + (size_t)(bn0 + r1) * K + s1 * 8;
    const int d0 = r0 * SKP + s0 * 8;
    const int d1 = r1 * SKP + s1 * 8;

    float acc[2][8][4];
#pragma unroll
    for (int i = 0; i < 2; i++)
#pragma unroll
        for (int j = 0; j < 8; j++)
#pragma unroll
            for (int c = 0; c < 4; c++) acc[i][j][c] = 0.0f;

    auto prefetch = [&](int it) {
        const int st = it & 1;
        const int k0 = it * 32;
        __nv_bfloat16* base = sm + st * STG;
        cpasync16(base + d0, gA0 + k0);
        cpasync16(base + d1, gA1 + k0);
        cpasync16(base + ARR + d0, gAl0 + k0);
        cpasync16(base + ARR + d1, gAl1 + k0);
        cpasync16(base + 2 * ARR + d0, gB0 + k0);
        cpasync16(base + 2 * ARR + d1, gB1 + k0);
        cpasync16(base + 3 * ARR + d0, gBl0 + k0);
        cpasync16(base + 3 * ARR + d1, gBl1 + k0);
        CP_COMMIT();
    };

    const int NIT = K / 32;
    prefetch(0);

    for (int it = 0; it < NIT; it++) {
        CP_WAIT0();            // stage it data arrived (only group in flight)
        __syncthreads();       // ...and stage (it+1)&1 fully drained by all warps
        if (it + 1 < NIT) prefetch(it + 1);

        const int st = it & 1;
        const uint32_t stOff = (uint32_t)(st * STG * 2);
        const uint32_t aBase = stOff + (uint32_t)(wm * 32) * (SKP * 2) + a_lane;
        const uint32_t bBase = stOff + (uint32_t)(wn * 64) * (SKP * 2) + b_lane;

#pragma unroll
        for (int ks = 0; ks < 2; ks++) {
            const uint32_t kb = (uint32_t)(ks * 32);
            uint32_t ah[2][4], al[2][4];
#pragma unroll
            for (int mt = 0; mt < 2; mt++) {
                const uint32_t off = aBase + (uint32_t)(mt * 16) * (SKP * 2) + kb;
                LDSM4(ah[mt], sAh_u + off);
                LDSM4(al[mt], sAl_u + off);
            }
#pragma unroll
            for (int p = 0; p < 4; p++) {
                uint32_t bh[4], bl[4];
                const uint32_t off = bBase + (uint32_t)(p * 16) * (SKP * 2) + kb;
                LDSM4(bh, sBh_u + off);
                LDSM4(bl, sBl_u + off);
#pragma unroll
                for (int mt = 0; mt < 2; mt++) {
#pragma unroll
                    for (int qq = 0; qq < 2; qq++) {
                        const int nt = p * 2 + qq;
                        const int q2 = qq * 2;
                        MMA16816(acc[mt][nt], ah[mt], bh[q2], bh[q2 + 1]);
                        MMA16816(acc[mt][nt], ah[mt], bl[q2], bl[q2 + 1]);
                        MMA16816(acc[mt][nt], al[mt], bh[q2], bh[q2 + 1]);
                    }
                }
            }
        }
    }

    const int gid = lane >> 2, tig = lane & 3;
#pragma unroll
    for (int mt = 0; mt < 2; mt++) {
#pragma unroll
        for (int nt = 0; nt < 8; nt++) {
            const int m = bm0 + wm * 32 + mt * 16 + gid;
            const int n = bn0 + wn * 64 + nt * 8 + tig * 2;
            const float b0 = bias[n], b1 = bias[n + 1];
            const float v00 = acc[mt][nt][0] + b0, v01 = acc[mt][nt][1] + b1;
            const float v10 = acc[mt][nt][2] + b0, v11 = acc[mt][nt][3] + b1;
            if (MODE == 0) {
                const int which = n >> 10;
                const int cc = n & 1023;
                const int h = cc >> 6, d = cc & 63;
                __nv_bfloat16 *dh, *dl;
                if (which == 0)      { dh = g_qh; dl = g_ql; }
                else if (which == 1) { dh = g_kh; dl = g_kl; }
                else                 { dh = g_vh; dl = g_vl; }
                const int bbi0 = m >> 10, nr0 = m & 1023;
                const int bbi1 = (m + 8) >> 10, nr1 = (m + 8) & 1023;
                uint32_t hh, ll;
                split2(v00, v01, hh, ll);
                size_t off0 = (size_t)(((bbi0 * Hh) + h) * Nn + nr0) * HD + d;
                *(uint32_t*)(dh + off0) = hh; *(uint32_t*)(dl + off0) = ll;
                split2(v10, v11, hh, ll);
                size_t off1 = (size_t)(((bbi1 * Hh) + h) * Nn + nr1) * HD + d;
                *(uint32_t*)(dh + off1) = hh; *(uint32_t*)(dl + off1) = ll;
            } else {
                *(float2*)(out + (size_t)m * Nout + n) = make_float2(v00, v01);
                *(float2*)(out + (size_t)(m + 8) * Nout + n) = make_float2(v10, v11);
            }
        }
    }
}

// ---------------------------------------------------------------------------
// Tensor-core fused attention (split bf16, 3-MMA) — unchanged from R7
// ---------------------------------------------------------------------------
#define SKP2 72
#define RS2 (SKP2 * 2)
#define OFF_QH 0
#define OFF_QL 9216
#define OFF_KH 18432
#define OFF_KL 27648
#define OFF_VH 36864
#define OFF_VL 46080
#define KV_STG 4608
#define ATTN_SMEM (55296 * 2)

__global__ __launch_bounds__(256, 1) void attn_mma_kernel(
    const float* __restrict__ diag_strength,
    const float* __restrict__ band_bias,
    const float* __restrict__ noise,
    const unsigned char* __restrict__ mask)
{
    extern __shared__ __nv_bfloat16 sm2[];

    const int tid = threadIdx.x;
    const int lane = tid & 31;
    const int warp = tid >> 5;
    const int nb = blockIdx.x;
    const int h = blockIdx.y;
    const int b = blockIdx.z;
    const bool causal = (h < NC);
    const float ds = causal ? diag_strength[b * NC + h] : 0.0f;
    const int bh = b * Hh + h;

    const int g = lane >> 2, t = lane & 3;
    const int q0 = nb * 128 + warp * 16;
    const int rg0 = q0 + g, rg1 = q0 + g + 8;
    const int diagtile = q0 >> 6;
    const int ntiles = causal ? (2 * nb + 2) : 16;

    const size_t qg = ((size_t)bh * Nn + nb * 128) * HD;
#pragma unroll
    for (int j = 0; j < 4; j++) {
        const int c = tid + j * 256;
        const int row = c >> 3, c8 = c & 7;
        const int dd = row * SKP2 + c8 * 8;
        const size_t sg = qg + row * HD + c8 * 8;
        cpasync16(sm2 + OFF_QH + dd, g_qh + sg);
        cpasync16(sm2 + OFF_QL + dd, g_ql + sg);
    }
    auto prefetchKV = [&](int mb) {
        const int st = mb & 1;
        const size_t kv = ((size_t)bh * Nn + mb * 64) * HD;
#pragma unroll
        for (int j = 0; j < 2; j++) {
            const int c = tid + j * 256;
            const int row = c >> 3, c8 = c & 7;
            const int dd = st * KV_STG + row * SKP2 + c8 * 8;
            const size_t sg = kv + row * HD + c8 * 8;
            cpasync16(sm2 + OFF_KH + dd, g_kh + sg);
            cpasync16(sm2 + OFF_KL + dd, g_kl + sg);
            cpasync16(sm2 + OFF_VH + dd, g_vh + sg);
            cpasync16(sm2 + OFF_VL + dd, g_vl + sg);
        }
        CP_COMMIT();
    };
    prefetchKV(0);
    CP_WAIT0();
    __syncthreads();

    const uint32_t sQh_u = (uint32_t)__cvta_generic_to_shared(sm2 + OFF_QH);
    const uint32_t sQl_u = (uint32_t)__cvta_generic_to_shared(sm2 + OFF_QL);
    const uint32_t sKh_u = (uint32_t)__cvta_generic_to_shared(sm2 + OFF_KH);
    const uint32_t sKl_u = (uint32_t)__cvta_generic_to_shared(sm2 + OFF_KL);
    const uint32_t sVh_u = (uint32_t)__cvta_generic_to_shared(sm2 + OFF_VH);
    const uint32_t sVl_u = (uint32_t)__cvta_generic_to_shared(sm2 + OFF_VL);

    const uint32_t a_lane = (uint32_t)((lane & 15) * RS2 + (lane >> 4) * 16);
    const uint32_t b_lane = (uint32_t)(((lane & 7) + ((lane >> 4) << 3)) * RS2
                                       + ((lane >> 3) & 1) * 16);

    uint32_t qfh[4][4], qfl[4][4];
    {
        const uint32_t qa = (uint32_t)(warp * 16) * RS2 + a_lane;
#pragma unroll
        for (int ks = 0; ks < 4; ks++) {
            LDSM4(qfh[ks], sQh_u + qa + ks * 32);
            LDSM4(qfl[ks], sQl_u + qa + ks * 32);
        }
    }

    float o[8][4];
#pragma unroll
    for (int i = 0; i < 8; i++)
#pragma unroll
        for (int j = 0; j < 4; j++) o[i][j] = 0.0f;
    float rmax0 = NEG_BIG, rmax1 = NEG_BIG, rsum0 = 0.0f, rsum1 = 0.0f;

    const size_t nm_base = (size_t)bh << 20;
    const float* bbp = causal ? band_bias : (band_bias + ((size_t)(h - NC) << 20));

    for (int mb = 0; mb < ntiles; mb++) {
        if (mb + 1 < ntiles) prefetchKV(mb + 1);

        const bool active = !(causal && mb > diagtile);
        if (active) {
            const uint32_t kst = (uint32_t)((mb & 1) * KV_STG * 2);

            float s[8][4];
#pragma unroll
            for (int i = 0; i < 8; i++)
#pragma unroll
                for (int j = 0; j < 4; j++) s[i][j] = 0.0f;
#pragma unroll
            for (int ks = 0; ks < 4; ks++) {
                uint32_t kfh[4][4], kfl[4][4];
#pragma unroll
                for (int p = 0; p < 4; p++) {
                    const uint32_t off = kst + (uint32_t)(p * 16) * RS2 + b_lane + ks * 32;
                    LDSM4(kfh[p], sKh_u + off);
                    LDSM4(kfl[p], sKl_u + off);
                }
#pragma unroll
                for (int p = 0; p < 4; p++) {
#pragma unroll
                    for (int qq = 0; qq < 2; qq++) {
                        const int nt = p * 2 + qq;
                        const int q2 = qq * 2;
                        MMA16816(s[nt], qfh[ks], kfh[p][q2], kfh[p][q2 + 1]);
                        MMA16816(s[nt], qfh[ks], kfl[p][q2], kfl[p][q2 + 1]);
                        MMA16816(s[nt], qfl[ks], kfh[p][q2], kfh[p][q2 + 1]);
                    }
                }
            }

            const int cb0 = mb * 64 + t * 2;
#pragma unroll
            for (int nt = 0; nt < 8; nt++) {
                const int c = cb0 + nt * 8;
                const size_t o0 = nm_base + ((size_t)rg0 << 10) + c;
                const size_t o1 = nm_base + ((size_t)rg1 << 10) + c;
                const float2 nz0 = *(const float2*)(noise + o0);
                const float2 nz1 = *(const float2*)(noise + o1);
                const uchar2 m0 = *(const uchar2*)(mask + o0);
                const uchar2 m1 = *(const uchar2*)(mask + o1);
                s[nt][0] = s[nt][0] * SCALEF + (m0.x ? nz0.x : 0.0f);
                s[nt][1] = s[nt][1] * SCALEF + (m0.y ? nz0.y : 0.0f);
                s[nt][2] = s[nt][2] * SCALEF + (m1.x ? nz1.x : 0.0f);
                s[nt][3] = s[nt][3] * SCALEF + (m1.y ? nz1.y : 0.0f);
                if (!causal) {
                    const float2 b0v = *(const float2*)(bbp + ((size_t)rg0 << 10) + c);
                    const float2 b1v = *(const float2*)(bbp + ((size_t)rg1 << 10) + c);
                    s[nt][0] += b0v.x; s[nt][1] += b0v.y;
                    s[nt][2] += b1v.x; s[nt][3] += b1v.y;
                } else if (mb == diagtile) {
                    if (c > rg0)           s[nt][0] = NEG_BIG;
                    else if (c == rg0)     s[nt][0] += ds;
                    if (c + 1 > rg0)       s[nt][1] = NEG_BIG;
                    else if (c + 1 == rg0) s[nt][1] += ds;
                    if (c > rg1)           s[nt][2] = NEG_BIG;
                    else if (c == rg1)     s[nt][2] += ds;
                    if (c + 1 > rg1)       s[nt][3] = NEG_BIG;
                    else if (c + 1 == rg1) s[nt][3] += ds;
                }
            }

            float mx0 = NEG_BIG, mx1 = NEG_BIG;
#pragma unroll
            for (int nt = 0; nt < 8; nt++) {
                mx0 = fmaxf(mx0, fmaxf(s[nt][0], s[nt][1]));
                mx1 = fmaxf(mx1, fmaxf(s[nt][2], s[nt][3]));
            }
            mx0 = fmaxf(mx0, __shfl_xor_sync(0xffffffffu, mx0, 1));
            mx0 = fmaxf(mx0, __shfl_xor_sync(0xffffffffu, mx0, 2));
            mx1 = fmaxf(mx1, __shfl_xor_sync(0xffffffffu, mx1, 1));
            mx1 = fmaxf(mx1, __shfl_xor_sync(0xffffffffu, mx1, 2));
            const float nm0 = fmaxf(rmax0, mx0);
            const float nm1 = fmaxf(rmax1, mx1);
            const float al0 = __expf(rmax0 - nm0);
            const float al1 = __expf(rmax1 - nm1);
            rmax0 = nm0; rmax1 = nm1;
            float ts0 = 0.0f, ts1 = 0.0f;
#pragma unroll
            for (int nt = 0; nt < 8; nt++) {
                s[nt][0] = __expf(s[nt][0] - nm0);
                s[nt][1] = __expf(s[nt][1] - nm0);
                s[nt][2] = __expf(s[nt][2] - nm1);
                s[nt][3] = __expf(s[nt][3] - nm1);
                ts0 += s[nt][0] + s[nt][1];
                ts1 += s[nt][2] + s[nt][3];
            }
            ts0 += __shfl_xor_sync(0xffffffffu, ts0, 1);
            ts0 += __shfl_xor_sync(0xffffffffu, ts0, 2);
            ts1 += __shfl_xor_sync(0xffffffffu, ts1, 1);
            ts1 += __shfl_xor_sync(0xffffffffu, ts1, 2);
            rsum0 = rsum0 * al0 + ts0;
            rsum1 = rsum1 * al1 + ts1;
#pragma unroll
            for (int nt = 0; nt < 8; nt++) {
                o[nt][0] *= al0; o[nt][1] *= al0;
                o[nt][2] *= al1; o[nt][3] *= al1;
            }

#pragma unroll
            for (int ks = 0; ks < 4; ks++) {
                uint32_t pah[4], pal[4];
                split2(s[2 * ks][0],     s[2 * ks][1],     pah[0], pal[0]);
                split2(s[2 * ks][2],     s[2 * ks][3],     pah[1], pal[1]);
                split2(s[2 * ks + 1][0], s[2 * ks + 1][1], pah[2], pal[2]);
                split2(s[2 * ks + 1][2], s[2 * ks + 1][3], pah[3], pal[3]);
#pragma unroll
                for (int dp = 0; dp < 4; dp++) {
                    uint32_t vfh[4], vfl[4];
                    const uint32_t off = kst + (uint32_t)(ks * 16) * RS2 + dp * 32 + a_lane;
                    LDSM4T(vfh, sVh_u + off);
                    LDSM4T(vfl, sVl_u + off);
                    const int nt0 = dp * 2, nt1 = dp * 2 + 1;
                    MMA16816(o[nt0], pah, vfh[0], vfh[1]);
                    MMA16816(o[nt0], pah, vfl[0], vfl[1]);
                    MMA16816(o[nt0], pal, vfh[0], vfh[1]);
                    MMA16816(o[nt1], pah, vfh[2], vfh[3]);
                    MMA16816(o[nt1], pah, vfl[2], vfl[3]);
                    MMA16816(o[nt1], pal, vfh[2], vfh[3]);
                }
            }
        }

        if (mb + 1 < ntiles) CP_WAIT0();
        __syncthreads();
    }

    const float inv0 = 1.0f / rsum0;
    const float inv1 = 1.0f / rsum1;
#pragma unroll
    for (int nt = 0; nt < 8; nt++) {
        const int d = h * HD + nt * 8 + t * 2;
        uint32_t hh, ll;
        const size_t off0 = ((size_t)b * Nn + rg0) * Cc + d;
        split2(o[nt][0] * inv0, o[nt][1] * inv0, hh, ll);
        *(uint32_t*)(g_ah + off0) = hh; *(uint32_t*)(g_al + off0) = ll;
        const size_t off1 = ((size_t)b * Nn + rg1) * Cc + d;
        split2(o[nt][2] * inv1, o[nt][3] * inv1, hh, ll);
        *(uint32_t*)(g_ah + off1) = hh; *(uint32_t*)(g_al + off1) = ll;
    }
}

// ---------------------------------------------------------------------------
extern "C" void kernel_launch(void* const* d_in, const int* in_sizes, int n_in,
                              void* d_out, int out_size)
{
    const float* x       = (const float*)d_in[0];
    const float* qkv_w   = (const float*)d_in[1];
    const float* qkv_b   = (const float*)d_in[2];
    const float* proj_w  = (const float*)d_in[3];
    const float* proj_b  = (const float*)d_in[4];
    const float* dstr    = (const float*)d_in[5];
    const float* bband   = (const float*)d_in[6];
    const float* noise   = (const float*)d_in[7];
    const unsigned char* smask = (const unsigned char*)d_in[8];
    float* out = (float*)d_out;

    cudaFuncSetAttribute(mma_gemm_kernel<0>,
                         cudaFuncAttributeMaxDynamicSharedMemorySize, SMEM_BYTES);
    cudaFuncSetAttribute(mma_gemm_kernel<1>,
                         cudaFuncAttributeMaxDynamicSharedMemorySize, SMEM_BYTES);
    cudaFuncSetAttribute(attn_mma_kernel,
                         cudaFuncAttributeMaxDynamicSharedMemorySize, ATTN_SMEM);

    // 1) split all fp32 inputs to (hi, lo) bf16 in one launch
    split_all_kernel<<<(XN + W1N + W2N) / 1024, 256>>>(x, qkv_w, proj_w);

    // 2) QKV projection -> split bf16 q/k/v
    dim3 g1(3072 / 128, 4096 / 128);
    mma_gemm_kernel<0><<<g1, 256, SMEM_BYTES>>>(qkv_b, nullptr, 3072);

    // 3) fused tensor-core attention -> split bf16 att
    dim3 g2(Nn / 128, Hh, Bb);
    attn_mma_kernel<<<g2, 256, ATTN_SMEM>>>(dstr, bband, noise, smask);

    // 4) output projection
    dim3 g3(1024 / 128, 4096 / 128);
    mma_gemm_kernel<1><<<g3, 256, SMEM_BYTES>>>(proj_b, out, 1024);
}